// round 12
// baseline (speedup 1.0000x reference)
#include <cuda_runtime.h>
#include <cuda_bf16.h>

#define BATCH 16
#define DIM   48
#define HID   16
#define CH    8
#define HH    256
#define WW    256
#define HW    (HH*WW)          // 65536
#define TILE  32
#define HT    34               // tile + halo
#define PITCH 35               // padded smem row pitch (conflict-free)

__constant__ float cW1[DIM*HID];
__constant__ float cB1[HID];
__constant__ float cGamma[CH];
__constant__ float cBeta[CH];
__constant__ float cDW[CH*9];
__constant__ float cDWB[CH];
__constant__ float cPW[CH*CH];
__constant__ float cPWB[CH];
__constant__ float cW2[CH*DIM];
__constant__ float cB2[DIM];

// scratch: front-half outputs (allowed: __device__ global arrays)
__device__ float g_x1[(size_t)BATCH*HW*CH];   // token-major  [b*HW+p][8]
__device__ float g_n [(size_t)BATCH*CH*HW];   // chan-planar  [(b*8+c)*HW+p]

// ---------------- exact GELU via A&S 7.1.26 + hardware MUFU ----------------
// erf |eps| <= 1.5e-7; ex2.approx / rcp.approx ~1e-7 rel. 2 MUFU + ~11 fma/alu ops.
// (MUFU count here is tiny: 64/token -> ~14us of chip MUFU time, fully hidden.)
__device__ __forceinline__ float gelu_fast(float u) {
    float e;
    asm("ex2.approx.f32 %0, %1;" : "=f"(e) : "f"(u * u * -0.72134752044f));  // e^{-u^2/2}
    float d = fmaf(fabsf(u), 0.23164190f, 1.0f);     // 1 + p*|u|/sqrt(2)
    float k;
    asm("rcp.approx.f32 %0, %1;" : "=f"(k) : "f"(d));
    // 0.5*(a1 k + a2 k^2 + ... + a5 k^5), coeffs pre-halved
    float poly = k * fmaf(k, fmaf(k, fmaf(k, fmaf(k, 0.5307027145f, -0.7265760135f),
                      0.7107068705f), -0.142248368f), 0.127414796f);
    float s   = poly * e;                            // 0.5*erfc(|u|/sqrt2)
    float Phi = 0.5f + copysignf(0.5f - s, u);
    return u * Phi;
}

// =================== Kernel 1: front (GEMM + 2xGELU + LN) ===================
__global__ void __launch_bounds__(256, 6)
front_kernel(const float* __restrict__ x) {
    __shared__ float sW1t[HID*DIM];      // transposed W1: [HID][DIM]

    const int tid = threadIdx.x;
    for (int i = tid; i < HID*DIM; i += 256) {
        int j = i / DIM, c = i % DIM;
        sW1t[i] = cW1[c*HID + j];
    }
    __syncthreads();

    const size_t tok = (size_t)blockIdx.x * 256 + tid;   // 0 .. BATCH*HW-1
    const float4* xp = (const float4*)(x + tok * DIM);

    float acc[HID];
    #pragma unroll
    for (int j = 0; j < HID; j++) acc[j] = cB1[j];

    #pragma unroll
    for (int c4 = 0; c4 < DIM/4; c4++) {
        float4 v = xp[c4];
        #pragma unroll
        for (int j = 0; j < HID; j++) {
            float4 w = *(const float4*)&sW1t[j*DIM + c4*4];
            float a = acc[j];
            a = fmaf(v.x, w.x, a);
            a = fmaf(v.y, w.y, a);
            a = fmaf(v.z, w.z, a);
            a = fmaf(v.w, w.w, a);
            acc[j] = a;
        }
    }

    #pragma unroll
    for (int j = 0; j < HID; j++) acc[j] = gelu_fast(gelu_fast(acc[j]));

    // x1 half -> token-major scratch (32B contiguous per thread)
    float4* x1p = (float4*)(g_x1 + tok * CH);
    x1p[0] = make_float4(acc[0], acc[1], acc[2], acc[3]);
    x1p[1] = make_float4(acc[4], acc[5], acc[6], acc[7]);

    // layernorm over acc[8..16) -> channel-planar scratch
    float m = 0.f;
    #pragma unroll
    for (int j = 0; j < CH; j++) m += acc[CH + j];
    m *= (1.0f/CH);
    float var = 0.f;
    #pragma unroll
    for (int j = 0; j < CH; j++) { float dd = acc[CH+j] - m; var = fmaf(dd, dd, var); }
    var *= (1.0f/CH);
    float is = rsqrtf(var + 1e-5f);

    const size_t b = tok >> 16;          // tok / HW
    const size_t p = tok & (HW - 1);     // tok % HW
    #pragma unroll
    for (int c = 0; c < CH; c++)
        g_n[((b*CH + c) << 16) + p] = (acc[CH+c] - m) * is * cGamma[c] + cBeta[c];
}

// =================== Kernel 2: conv + gate + back GEMM ===================
__global__ void __launch_bounds__(256, 4)
back_kernel(float* __restrict__ out) {
    __shared__ float n_s[CH][HT*PITCH];   // 38080 B
    __shared__ float sW2t[DIM*CH];        // transposed W2: [DIM][CH]

    const int b   = blockIdx.z;
    const int bx  = blockIdx.x * TILE;
    const int by  = blockIdx.y * TILE;
    const int tid = threadIdx.x;
    const int iy  = tid >> 3;            // 0..31
    const int ix1 = (tid & 7) << 2;      // 0,4,...,28 (4 px per thread)
    const int gy  = by + iy;
    const int gx0 = bx + ix1;

    // stage all DIM*CH=384 entries with a 256-thread block
    for (int i = tid; i < DIM*CH; i += 256) {
        int o = i >> 3, j = i & 7;
        sW2t[i] = cW2[j*DIM + o];
    }

    // ---- load n tile + halo from global (L2-resident) ----
    const float* nb = g_n + ((size_t)b*CH << 16);
    for (int i = tid; i < CH*HT*HT; i += 256) {
        int c  = i / (HT*HT);
        int r  = i % (HT*HT);
        int hy = r / HT, hx = r % HT;
        int gy2 = by + hy - 1, gx2 = bx + hx - 1;
        float v = 0.f;
        if (gy2 >= 0 && gy2 < HH && gx2 >= 0 && gx2 < WW)
            v = nb[((size_t)c << 16) + gy2*WW + gx2];
        n_s[c][hy*PITCH + hx] = v;
    }
    __syncthreads();

    // ---- x1 for this thread's 4 pixels ----
    float g[4][CH];
    {
        const float4* x1p = (const float4*)(g_x1 + (((size_t)b << 16) + gy*WW + gx0) * CH);
        #pragma unroll
        for (int p = 0; p < 4; p++) {
            float4 a = x1p[2*p], c = x1p[2*p+1];
            g[p][0]=a.x; g[p][1]=a.y; g[p][2]=a.z; g[p][3]=a.w;
            g[p][4]=c.x; g[p][5]=c.y; g[p][6]=c.z; g[p][7]=c.w;
        }
    }

    // ---- dw-conv 3x3 + pw-conv 1x1 + gate ----
    #pragma unroll
    for (int p = 0; p < 4; p++) {
        const int base = (iy+1)*PITCH + (ix1+p+1);
        float nc[CH], sp[CH];
        #pragma unroll
        for (int c = 0; c < CH; c++) {
            nc[c] = n_s[c][base];
            float s = cDWB[c];
            #pragma unroll
            for (int dy = 0; dy < 3; dy++) {
                #pragma unroll
                for (int dx = 0; dx < 3; dx++) {
                    s = fmaf(cDW[c*9 + dy*3 + dx],
                             n_s[c][base + (dy-1)*PITCH + (dx-1)], s);
                }
            }
            sp[c] = s;
        }
        #pragma unroll
        for (int c = 0; c < CH; c++) {
            float t = cPWB[c];
            #pragma unroll
            for (int k = 0; k < CH; k++) t = fmaf(cPW[c*CH + k], nc[k], t);
            g[p][c] *= sp[c] * t;        // g = x1 * (sp * ch)
        }
    }

    // ---- back GEMM g[8] @ W2[8x48] + b2, float4 stores per channel plane ----
    float* outb = out + ((size_t)b*DIM*HH + gy)*WW + gx0;
    #pragma unroll
    for (int o = 0; o < DIM; o++) {
        float4 wa = *(const float4*)&sW2t[o*CH];
        float4 wb = *(const float4*)&sW2t[o*CH + 4];
        float bo = cB2[o];
        float vv[4];
        #pragma unroll
        for (int p = 0; p < 4; p++) {
            float s = bo;
            s = fmaf(g[p][0], wa.x, s);
            s = fmaf(g[p][1], wa.y, s);
            s = fmaf(g[p][2], wa.z, s);
            s = fmaf(g[p][3], wa.w, s);
            s = fmaf(g[p][4], wb.x, s);
            s = fmaf(g[p][5], wb.y, s);
            s = fmaf(g[p][6], wb.z, s);
            s = fmaf(g[p][7], wb.w, s);
            vv[p] = s;
        }
        *(float4*)(outb + (size_t)o*HW) = make_float4(vv[0], vv[1], vv[2], vv[3]);
    }
}

extern "C" void kernel_launch(void* const* d_in, const int* in_sizes, int n_in,
                              void* d_out, int out_size) {
    cudaMemcpyToSymbolAsync(cW1,    d_in[1],  sizeof(cW1),    0, cudaMemcpyDeviceToDevice, 0);
    cudaMemcpyToSymbolAsync(cB1,    d_in[2],  sizeof(cB1),    0, cudaMemcpyDeviceToDevice, 0);
    cudaMemcpyToSymbolAsync(cGamma, d_in[3],  sizeof(cGamma), 0, cudaMemcpyDeviceToDevice, 0);
    cudaMemcpyToSymbolAsync(cBeta,  d_in[4],  sizeof(cBeta),  0, cudaMemcpyDeviceToDevice, 0);
    cudaMemcpyToSymbolAsync(cDW,    d_in[5],  sizeof(cDW),    0, cudaMemcpyDeviceToDevice, 0);
    cudaMemcpyToSymbolAsync(cDWB,   d_in[6],  sizeof(cDWB),   0, cudaMemcpyDeviceToDevice, 0);
    cudaMemcpyToSymbolAsync(cPW,    d_in[7],  sizeof(cPW),    0, cudaMemcpyDeviceToDevice, 0);
    cudaMemcpyToSymbolAsync(cPWB,   d_in[8],  sizeof(cPWB),   0, cudaMemcpyDeviceToDevice, 0);
    cudaMemcpyToSymbolAsync(cW2,    d_in[9],  sizeof(cW2),    0, cudaMemcpyDeviceToDevice, 0);
    cudaMemcpyToSymbolAsync(cB2,    d_in[10], sizeof(cB2),    0, cudaMemcpyDeviceToDevice, 0);

    const float* x = (const float*)d_in[0];
    float* out = (float*)d_out;

    front_kernel<<<BATCH*HW/256, 256>>>(x);                 // 4096 blocks
    dim3 grid2(WW/TILE, HH/TILE, BATCH);                    // (8, 8, 16)
    back_kernel<<<grid2, 256>>>(out);
}